// round 4
// baseline (speedup 1.0000x reference)
#include <cuda_runtime.h>
#include <cstdint>
#include <cfloat>

// Problem constants
#define NTOK 4096      // B*S = 2*2048
#define DMODEL 768
#define MDB 32768
#define KSEL 16
#define KSHORT 32
#define NHEAD 12
#define HDIM 64
#define DFF 3072

// ---------------- scratch (device globals; no allocations allowed) ----------
__device__ float g_h1[NTOK * DMODEL];
__device__ float g_q[NTOK * DMODEL];
__device__ float g_scores[(size_t)NTOK * MDB];
__device__ int   g_idx32[NTOK * KSHORT];
__device__ int   g_idx[NTOK * KSEL];
__device__ float g_attn[NTOK * DMODEL];
__device__ float g_res2[NTOK * DMODEL];
__device__ float g_h2[NTOK * DMODEL];
__device__ float g_ff[NTOK * DFF];

// ---------------- helpers ----------------------------------------------------
__device__ __forceinline__ float gelu_new(float x) {
    float x3 = x * x * x;
    float u = 0.7978845608028654f * (x + 0.044715f * x3);
    return 0.5f * x * (1.0f + tanhf(u));
}

__device__ __forceinline__ uint32_t f2tf32(float x) {
    uint32_t u;
    asm("cvt.rna.tf32.f32 %0, %1;" : "=r"(u) : "f"(x));
    return u;
}

__device__ __forceinline__ void mma_tf32(float* d, const uint32_t* a, uint32_t b0, uint32_t b1) {
    asm volatile(
        "mma.sync.aligned.m16n8k8.row.col.f32.tf32.tf32.f32 "
        "{%0,%1,%2,%3}, {%4,%5,%6,%7}, {%8,%9}, {%0,%1,%2,%3};\n"
        : "+f"(d[0]), "+f"(d[1]), "+f"(d[2]), "+f"(d[3])
        : "r"(a[0]), "r"(a[1]), "r"(a[2]), "r"(a[3]), "r"(b0), "r"(b1));
}

// ---------------- layernorm ---------------------------------------------------
__global__ void ln_kernel(const float* __restrict__ x,
                          const float* __restrict__ g,
                          const float* __restrict__ b,
                          float* __restrict__ out) {
    int row = blockIdx.x;
    int t = threadIdx.x;
    const float* xr = x + (size_t)row * DMODEL;
    float v[3];
#pragma unroll
    for (int i = 0; i < 3; i++) v[i] = xr[t + i * 256];
    float s = 0.f, s2 = 0.f;
#pragma unroll
    for (int i = 0; i < 3; i++) { s += v[i]; s2 += v[i] * v[i]; }
#pragma unroll
    for (int o = 16; o; o >>= 1) {
        s  += __shfl_down_sync(0xffffffffu, s, o);
        s2 += __shfl_down_sync(0xffffffffu, s2, o);
    }
    __shared__ float ws[8], ws2[8];
    int w = t >> 5, l = t & 31;
    if (l == 0) { ws[w] = s; ws2[w] = s2; }
    __syncthreads();
    if (t == 0) {
        float a = 0.f, a2 = 0.f;
#pragma unroll
        for (int i = 0; i < 8; i++) { a += ws[i]; a2 += ws2[i]; }
        float mu = a / DMODEL;
        ws[0] = mu;
        ws2[0] = a2 / DMODEL - mu * mu;
    }
    __syncthreads();
    float mu = ws[0];
    float rstd = rsqrtf(ws2[0] + 1e-5f);
    float* orow = out + (size_t)row * DMODEL;
#pragma unroll
    for (int i = 0; i < 3; i++) {
        int c = t + i * 256;
        orow[c] = (v[i] - mu) * rstd * g[c] + b[c];
    }
}

// ---------------- tf32 tensor-core GEMM (optional 3xTF32 emulation) ----------
// C[M, Ncols] = A[M, Kd] x B (+ epilogue). lda = Kd, ldc = Ncols.
// TRANSB=false: B is [Kd, ldb], cols n0..n0+127 used.
// TRANSB=true : B is [Ncols, ldb=Kd]; C = A * B^T.
// EPI: 0 none, 1 +bias, 2 +bias+gelu, 3 +bias+res
// X3: 3xTF32 split (hi/lo) for ~fp32 accuracy.
// Block tile 128x128, K-step 16, 256 threads, 8 warps (4Mx2N), warp tile 32x64.
template <bool TRANSB, int EPI, bool X3>
__global__ __launch_bounds__(256, 2)
void mma_gemm(const float* __restrict__ A, const float* __restrict__ B,
              const float* __restrict__ bias, const float* __restrict__ res,
              float* __restrict__ C, int Kd, int ldb, int Ncols) {
    constexpr int NP = X3 ? 2 : 1;
    __shared__ uint32_t As[NP][16][132];   // [part][k][m]
    __shared__ uint32_t Bs[NP][16][132];   // [part][k][n]
    int tid = threadIdx.x;
    int lane = tid & 31, warp = tid >> 5;
    int warpM = warp >> 1, warpN = warp & 1;
    int m0 = blockIdx.y * 128, n0 = blockIdx.x * 128;

    float acc[2][8][4];
#pragma unroll
    for (int i = 0; i < 2; i++)
#pragma unroll
        for (int j = 0; j < 8; j++)
#pragma unroll
            for (int q = 0; q < 4; q++) acc[i][j][q] = 0.f;

    // gmem->smem mapping (8 floats per thread per operand per iter)
    int arow = tid >> 1;             // 0..127 (m)
    int acol = (tid & 1) * 8;        // 0/8 (k)
    const float* Ag = A + (size_t)(m0 + arow) * Kd + acol;
    const float* Bg;
    int brow, bcol;
    if (TRANSB) {
        brow = tid >> 1; bcol = (tid & 1) * 8;            // brow=n, bcol=k
        Bg = B + (size_t)(n0 + brow) * ldb + bcol;
    } else {
        brow = tid >> 4; bcol = (tid & 15) * 8;           // brow=k, bcol=n
        Bg = B + (size_t)brow * ldb + n0 + bcol;
    }

    int r = lane >> 2, c = lane & 3;

    for (int k0 = 0; k0 < Kd; k0 += 16) {
        float4 a4[2], b4[2];
#pragma unroll
        for (int i = 0; i < 2; i++) a4[i] = *(const float4*)(Ag + k0 + i * 4);
        if (TRANSB) {
#pragma unroll
            for (int i = 0; i < 2; i++) b4[i] = *(const float4*)(Bg + k0 + i * 4);
        } else {
#pragma unroll
            for (int i = 0; i < 2; i++) b4[i] = *(const float4*)(Bg + (size_t)k0 * ldb + i * 4);
        }
        __syncthreads();
#pragma unroll
        for (int i = 0; i < 2; i++) {
            float av[4] = {a4[i].x, a4[i].y, a4[i].z, a4[i].w};
#pragma unroll
            for (int j = 0; j < 4; j++) {
                uint32_t hi = f2tf32(av[j]);
                As[0][acol + i * 4 + j][arow] = hi;
                if (X3) As[1][acol + i * 4 + j][arow] = f2tf32(av[j] - __uint_as_float(hi));
            }
        }
#pragma unroll
        for (int i = 0; i < 2; i++) {
            float bv[4] = {b4[i].x, b4[i].y, b4[i].z, b4[i].w};
#pragma unroll
            for (int j = 0; j < 4; j++) {
                uint32_t hi = f2tf32(bv[j]);
                if (TRANSB) {
                    Bs[0][bcol + i * 4 + j][brow] = hi;
                    if (X3) Bs[1][bcol + i * 4 + j][brow] = f2tf32(bv[j] - __uint_as_float(hi));
                } else {
                    Bs[0][brow][bcol + i * 4 + j] = hi;
                    if (X3) Bs[1][brow][bcol + i * 4 + j] = f2tf32(bv[j] - __uint_as_float(hi));
                }
            }
        }
        __syncthreads();

#pragma unroll
        for (int kk = 0; kk < 16; kk += 8) {
            uint32_t afh[2][4], afl[2][4];
#pragma unroll
            for (int mi = 0; mi < 2; mi++) {
                int mb = warpM * 32 + mi * 16;
                afh[mi][0] = As[0][kk + c][mb + r];
                afh[mi][1] = As[0][kk + c][mb + 8 + r];
                afh[mi][2] = As[0][kk + 4 + c][mb + r];
                afh[mi][3] = As[0][kk + 4 + c][mb + 8 + r];
                if (X3) {
                    afl[mi][0] = As[1][kk + c][mb + r];
                    afl[mi][1] = As[1][kk + c][mb + 8 + r];
                    afl[mi][2] = As[1][kk + 4 + c][mb + r];
                    afl[mi][3] = As[1][kk + 4 + c][mb + 8 + r];
                }
            }
#pragma unroll
            for (int ni = 0; ni < 8; ni++) {
                int nb = warpN * 64 + ni * 8;
                uint32_t b0h = Bs[0][kk + c][nb + r];
                uint32_t b1h = Bs[0][kk + 4 + c][nb + r];
                mma_tf32(acc[0][ni], afh[0], b0h, b1h);
                mma_tf32(acc[1][ni], afh[1], b0h, b1h);
                if (X3) {
                    uint32_t b0l = Bs[1][kk + c][nb + r];
                    uint32_t b1l = Bs[1][kk + 4 + c][nb + r];
                    mma_tf32(acc[0][ni], afl[0], b0h, b1h);
                    mma_tf32(acc[1][ni], afl[1], b0h, b1h);
                    mma_tf32(acc[0][ni], afh[0], b0l, b1l);
                    mma_tf32(acc[1][ni], afh[1], b0l, b1l);
                }
            }
        }
    }

    // epilogue
    int cb = (lane & 3) * 2;
#pragma unroll
    for (int mi = 0; mi < 2; mi++) {
        int row0 = m0 + warpM * 32 + mi * 16 + r;
#pragma unroll
        for (int ni = 0; ni < 8; ni++) {
            int col = n0 + warpN * 64 + ni * 8 + cb;
#pragma unroll
            for (int half = 0; half < 2; half++) {
                int row = row0 + half * 8;
                size_t base = (size_t)row * Ncols + col;
                float v0 = acc[mi][ni][half * 2 + 0];
                float v1 = acc[mi][ni][half * 2 + 1];
                if (EPI >= 1) { v0 += bias[col]; v1 += bias[col + 1]; }
                if (EPI == 2) { v0 = gelu_new(v0); v1 = gelu_new(v1); }
                if (EPI == 3) {
                    float2 rr = *(const float2*)(res + base);
                    v0 += rr.x; v1 += rr.y;
                }
                float2 o; o.x = v0; o.y = v1;
                *(float2*)(C + base) = o;
            }
        }
    }
}

// ---------------- top-32 shortlist per row over 32768 scores -----------------
__global__ void topk32_kernel() {
    int row = blockIdx.x;
    int t = threadIdx.x;
    const float* s = g_scores + (size_t)row * MDB;

    float lv[KSHORT];
    int   li[KSHORT];
#pragma unroll
    for (int i = 0; i < KSHORT; i++) { lv[i] = -FLT_MAX; li[i] = 0x7fffffff; }

    for (int j = t; j < MDB; j += 256) {
        float v = s[j];
        if (v > lv[KSHORT - 1]) {
            int p = KSHORT - 1;
            while (p > 0 && lv[p - 1] < v) {
                lv[p] = lv[p - 1]; li[p] = li[p - 1]; p--;
            }
            lv[p] = v; li[p] = j;
        }
    }

    __shared__ float cv[256];
    __shared__ int   ci[256];
    __shared__ int   ctid[256];
    int p = 0;
    for (int rnd = 0; rnd < KSHORT; rnd++) {
        cv[t] = (p < KSHORT) ? lv[p] : -FLT_MAX;
        ci[t] = (p < KSHORT) ? li[p] : 0x7fffffff;
        ctid[t] = t;
        __syncthreads();
        for (int off = 128; off > 0; off >>= 1) {
            if (t < off) {
                float a = cv[t], b = cv[t + off];
                if (b > a || (b == a && ci[t + off] < ci[t])) {
                    cv[t] = b; ci[t] = ci[t + off]; ctid[t] = ctid[t + off];
                }
            }
            __syncthreads();
        }
        int wt = ctid[0];
        if (t == 0) g_idx32[row * KSHORT + rnd] = ci[0];
        __syncthreads();
        if (t == wt) p++;
    }
}

// ---------------- fp32 rescore of 32 candidates, exact top-16 ----------------
__global__ void rescore_kernel(const float* __restrict__ dbk) {
    int tok = blockIdx.x;
    int t = threadIdx.x;
    int w = t >> 5, l = t & 31;

    __shared__ float qs[DMODEL];
    __shared__ int   cands[KSHORT];
    __shared__ float svals[KSHORT];

    if (t < KSHORT) cands[t] = g_idx32[tok * KSHORT + t];
    for (int i = t; i < DMODEL; i += 256) qs[i] = g_q[(size_t)tok * DMODEL + i];
    __syncthreads();

#pragma unroll
    for (int cc = 0; cc < 4; cc++) {
        int cidx = w * 4 + cc;
        const float* kr = dbk + (size_t)cands[cidx] * DMODEL;
        float d = 0.f;
        for (int j = l; j < DMODEL; j += 32) d += qs[j] * kr[j];
#pragma unroll
        for (int o = 16; o; o >>= 1) d += __shfl_xor_sync(0xffffffffu, d, o);
        if (l == 0) svals[cidx] = d;
    }
    __syncthreads();

    if (t < 32) {
        float v = svals[t];
        int   ci = cands[t];
#pragma unroll
        for (int rnd = 0; rnd < KSEL; rnd++) {
            float bv = v;
            int bl = t;
#pragma unroll
            for (int o = 16; o; o >>= 1) {
                float ov = __shfl_xor_sync(0xffffffffu, bv, o);
                int   ol = __shfl_xor_sync(0xffffffffu, bl, o);
                if (ov > bv || (ov == bv && ol < bl)) { bv = ov; bl = ol; }
            }
            int wci = __shfl_sync(0xffffffffu, ci, bl);
            if (t == 0) g_idx[tok * KSEL + rnd] = wci;
            if (t == bl) v = -FLT_MAX;
        }
    }
}

// ---------------- gather + per-token softmax attention ------------------------
__global__ void attn_kernel(const float* __restrict__ dbk,
                            const float* __restrict__ dbv) {
    int tok = blockIdx.x;
    int t = threadIdx.x;
    int w = t >> 5, l = t & 31;

    __shared__ float qs[DMODEL];
    __shared__ int   idxs[KSEL];
    __shared__ float sc[NHEAD * KSEL];
    __shared__ float wts[NHEAD * KSEL];

    if (t < KSEL) idxs[t] = g_idx[tok * KSEL + t];
    for (int i = t; i < DMODEL; i += 128) qs[i] = g_q[(size_t)tok * DMODEL + i];
    __syncthreads();

    for (int pp = w * 48; pp < (w + 1) * 48; pp++) {
        int h = pp >> 4, k = pp & 15;
        const float* kr = dbk + (size_t)idxs[k] * DMODEL + h * HDIM;
        float2 kv = ((const float2*)kr)[l];
        float2 qv = ((const float2*)(qs + h * HDIM))[l];
        float d = kv.x * qv.x + kv.y * qv.y;
#pragma unroll
        for (int o = 16; o; o >>= 1) d += __shfl_xor_sync(0xffffffffu, d, o);
        if (l == 0) sc[pp] = d * 0.125f;
    }
    __syncthreads();

    if (t < NHEAD) {
        float mx = -FLT_MAX;
#pragma unroll
        for (int k = 0; k < KSEL; k++) mx = fmaxf(mx, sc[t * KSEL + k]);
        float sum = 0.f;
#pragma unroll
        for (int k = 0; k < KSEL; k++) {
            float e = expf(sc[t * KSEL + k] - mx);
            wts[t * KSEL + k] = e;
            sum += e;
        }
        float inv = 1.0f / sum;
#pragma unroll
        for (int k = 0; k < KSEL; k++) wts[t * KSEL + k] *= inv;
    }
    __syncthreads();

    float acc[6] = {0.f, 0.f, 0.f, 0.f, 0.f, 0.f};
    int hh[6];
#pragma unroll
    for (int j = 0; j < 6; j++) hh[j] = (t + j * 128) >> 6;
    for (int k = 0; k < KSEL; k++) {
        const float* vr = dbv + (size_t)idxs[k] * DMODEL;
#pragma unroll
        for (int j = 0; j < 6; j++) {
            acc[j] += wts[hh[j] * KSEL + k] * vr[t + j * 128];
        }
    }
    float* orow = g_attn + (size_t)tok * DMODEL;
#pragma unroll
    for (int j = 0; j < 6; j++) orow[t + j * 128] = acc[j];
}

// ---------------- launch ------------------------------------------------------
extern "C" void kernel_launch(void* const* d_in, const int* in_sizes, int n_in,
                              void* d_out, int out_size) {
    const float* prev     = (const float*)d_in[0];
    const float* db_keys  = (const float*)d_in[1];
    const float* db_vals  = (const float*)d_in[2];
    const float* ln1_g    = (const float*)d_in[3];
    const float* ln1_b    = (const float*)d_in[4];
    const float* c_attn_w = (const float*)d_in[5];
    const float* c_attn_b = (const float*)d_in[6];
    const float* c_proj_w = (const float*)d_in[7];
    const float* c_proj_b = (const float*)d_in[8];
    const float* ln2_g    = (const float*)d_in[9];
    const float* ln2_b    = (const float*)d_in[10];
    const float* fc_w     = (const float*)d_in[11];
    const float* fc_b     = (const float*)d_in[12];
    const float* proj_w   = (const float*)d_in[13];
    const float* proj_b   = (const float*)d_in[14];
    float* out = (float*)d_out;

    float *p_h1, *p_q, *p_scores, *p_attn, *p_res2, *p_h2, *p_ff;
    cudaGetSymbolAddress((void**)&p_h1, g_h1);
    cudaGetSymbolAddress((void**)&p_q, g_q);
    cudaGetSymbolAddress((void**)&p_scores, g_scores);
    cudaGetSymbolAddress((void**)&p_attn, g_attn);
    cudaGetSymbolAddress((void**)&p_res2, g_res2);
    cudaGetSymbolAddress((void**)&p_h2, g_h2);
    cudaGetSymbolAddress((void**)&p_ff, g_ff);

    // 1. LN1
    ln_kernel<<<NTOK, 256>>>(prev, ln1_g, ln1_b, p_h1);
    // 2. q projection — 3xTF32 (feeds attention logits; needs fp32 accuracy)
    mma_gemm<false, 1, true><<<dim3(DMODEL / 128, NTOK / 128), 256>>>(
        p_h1, c_attn_w, c_attn_b, nullptr, p_q, DMODEL, 3 * DMODEL, DMODEL);
    // 3. KNN scores — 1-pass tf32 (selection protected by fp32 rescore)
    mma_gemm<true, 0, false><<<dim3(MDB / 128, NTOK / 128), 256>>>(
        p_q, db_keys, nullptr, nullptr, p_scores, DMODEL, DMODEL, MDB);
    // 4. top-32 shortlist per token
    topk32_kernel<<<NTOK, 256>>>();
    // 5. exact fp32 rescore -> top-16
    rescore_kernel<<<NTOK, 256>>>(db_keys);
    // 6. gather + per-token memory attention
    attn_kernel<<<NTOK, 128>>>(db_keys, db_vals);
    // 7. c_proj + residual — 3xTF32
    mma_gemm<false, 3, true><<<dim3(DMODEL / 128, NTOK / 128), 256>>>(
        p_attn, c_proj_w, c_proj_b, prev, p_res2, DMODEL, DMODEL, DMODEL);
    // 8. LN2
    ln_kernel<<<NTOK, 256>>>(p_res2, ln2_g, ln2_b, p_h2);
    // 9. MLP fc + gelu — 3xTF32
    mma_gemm<false, 2, true><<<dim3(DFF / 128, NTOK / 128), 256>>>(
        p_h2, fc_w, fc_b, nullptr, p_ff, DMODEL, DFF, DFF);
    // 10. MLP proj + bias + residual2 -> out — 3xTF32
    mma_gemm<false, 3, true><<<dim3(DMODEL / 128, NTOK / 128), 256>>>(
        p_ff, proj_w, proj_b, p_res2, out, DFF, DMODEL, DMODEL);
}

// round 9
// speedup vs baseline: 1.6093x; 1.6093x over previous
#include <cuda_runtime.h>
#include <cuda_bf16.h>
#include <cstdint>
#include <cfloat>

// Problem constants
#define NTOK 4096      // B*S
#define DMODEL 768
#define MDB 32768
#define KSEL 16
#define KSHORT 32
#define NHEAD 12
#define HDIM 64
#define DFF 3072

// ---------------- scratch (device globals) -----------------------------------
__device__ float g_h1[NTOK * DMODEL];
__device__ float g_q[NTOK * DMODEL];
__device__ float g_scores[(size_t)NTOK * MDB];
__device__ int   g_idx32[NTOK * KSHORT];
__device__ int   g_idx[NTOK * KSEL];
__device__ float g_attn[NTOK * DMODEL];
__device__ float g_res2[NTOK * DMODEL];
__device__ float g_h2[NTOK * DMODEL];
__device__ float g_ff[NTOK * DFF];
__device__ __nv_bfloat16 g_keys_bf[(size_t)MDB * DMODEL];   // 48MB
__device__ __nv_bfloat16 g_qb[NTOK * DMODEL];               // scores A operand

// ---------------- helpers -----------------------------------------------------
__device__ __forceinline__ uint32_t cvta_smem(const void* p) {
    uint32_t a;
    asm("{ .reg .u64 t; cvta.to.shared.u64 t, %1; cvt.u32.u64 %0, t; }" : "=r"(a) : "l"(p));
    return a;
}
#define SW128(o) ((o) ^ (((o) >> 3) & 0x70))

__device__ __forceinline__ void mma_bf16(float* d, const uint32_t* a, uint32_t b0, uint32_t b1) {
    asm volatile(
        "mma.sync.aligned.m16n8k16.row.col.f32.bf16.bf16.f32 "
        "{%0,%1,%2,%3}, {%4,%5,%6,%7}, {%8,%9}, {%0,%1,%2,%3};"
        : "+f"(d[0]), "+f"(d[1]), "+f"(d[2]), "+f"(d[3])
        : "r"(a[0]), "r"(a[1]), "r"(a[2]), "r"(a[3]), "r"(b0), "r"(b1));
}

__device__ __forceinline__ float gelu_new(float x) {
    float x3 = x * x * x;
    float u = 0.7978845608028654f * (x + 0.044715f * x3);
    return 0.5f * x * (1.0f + tanhf(u));
}

// ---------------- bf16 tensor-core GEMM (scores only) -------------------------
// C[M, Ncols] fp32 = A[M, Kd] bf16 x B[Ncols, Kd]^T bf16
// CTA tile 128x128, K chunk 64, 8 warps (2M x 4N), warp tile 64x32,
// 4-stage cp.async ring. Kd % 64 == 0.
__global__ __launch_bounds__(256)
void bgemm(const __nv_bfloat16* __restrict__ A, const __nv_bfloat16* __restrict__ B,
           float* __restrict__ C, int Kd, int Ncols) {
    extern __shared__ char smem[];
    const int tid = threadIdx.x;
    const int lane = tid & 31, warp = tid >> 5;
    const int warpM = warp & 1, warpN = warp >> 1;
    const int m0 = blockIdx.x * 128, n0 = blockIdx.y * 128;
    uint32_t sb = cvta_smem(smem);
    const int nch = Kd >> 6;

    const int lr = tid >> 3, lc = tid & 7;

#define LOAD_STAGE(s, cc) do { \
    int _k0e = (cc) << 6; \
    uint32_t _as = sb + (s) * 32768u; \
    uint32_t _bs = _as + 16384u; \
    _Pragma("unroll") \
    for (int _i = 0; _i < 4; _i++) { \
        int _r = lr + _i * 32; \
        uint32_t _so = SW128((uint32_t)(_r * 128 + lc * 16)); \
        const void* _ga = A + (size_t)(m0 + _r) * Kd + _k0e + lc * 8; \
        asm volatile("cp.async.cg.shared.global [%0], [%1], 16;" :: "r"(_as + _so), "l"(_ga)); \
        const void* _gb = B + (size_t)(n0 + _r) * Kd + _k0e + lc * 8; \
        asm volatile("cp.async.cg.shared.global [%0], [%1], 16;" :: "r"(_bs + _so), "l"(_gb)); \
    } \
} while (0)

    float acc[4][4][4];
#pragma unroll
    for (int a = 0; a < 4; a++)
#pragma unroll
        for (int b = 0; b < 4; b++)
#pragma unroll
            for (int c = 0; c < 4; c++) acc[a][b][c] = 0.f;

    LOAD_STAGE(0, 0);
    asm volatile("cp.async.commit_group;" ::: "memory");
    LOAD_STAGE(1, 1);
    asm volatile("cp.async.commit_group;" ::: "memory");
    if (nch > 2) LOAD_STAGE(2, 2);
    asm volatile("cp.async.commit_group;" ::: "memory");

    for (int cc = 0; cc < nch; cc++) {
        asm volatile("cp.async.wait_group %0;" :: "n"(2) : "memory");
        __syncthreads();
        if (cc + 3 < nch) LOAD_STAGE((cc + 3) & 3, cc + 3);
        asm volatile("cp.async.commit_group;" ::: "memory");

        uint32_t as = sb + (uint32_t)(cc & 3) * 32768u;
        uint32_t bs = as + 16384u;
#pragma unroll
        for (int kt = 0; kt < 4; kt++) {
            uint32_t aF[4][4], bF[2][4];
#pragma unroll
            for (int mt = 0; mt < 4; mt++) {
                uint32_t off = (uint32_t)((warpM * 64 + mt * 16 + (lane & 15)) * 128
                                          + kt * 32 + (lane >> 4) * 16);
                uint32_t ad = as + SW128(off);
                asm volatile("ldmatrix.sync.aligned.m8n8.x4.shared.b16 {%0,%1,%2,%3}, [%4];"
                    : "=r"(aF[mt][0]), "=r"(aF[mt][1]), "=r"(aF[mt][2]), "=r"(aF[mt][3])
                    : "r"(ad));
            }
#pragma unroll
            for (int nt = 0; nt < 2; nt++) {
                int nrow = warpN * 32 + nt * 16 + ((lane >> 4) << 3) + (lane & 7);
                uint32_t off = (uint32_t)(nrow * 128 + kt * 32 + ((lane >> 3) & 1) * 16);
                uint32_t bd = bs + SW128(off);
                asm volatile("ldmatrix.sync.aligned.m8n8.x4.shared.b16 {%0,%1,%2,%3}, [%4];"
                    : "=r"(bF[nt][0]), "=r"(bF[nt][1]), "=r"(bF[nt][2]), "=r"(bF[nt][3])
                    : "r"(bd));
            }
#pragma unroll
            for (int mt = 0; mt < 4; mt++) {
#pragma unroll
                for (int nt = 0; nt < 2; nt++) {
                    mma_bf16(acc[mt][nt * 2],     aF[mt], bF[nt][0], bF[nt][1]);
                    mma_bf16(acc[mt][nt * 2 + 1], aF[mt], bF[nt][2], bF[nt][3]);
                }
            }
        }
    }

#pragma unroll
    for (int mt = 0; mt < 4; mt++) {
#pragma unroll
        for (int nn = 0; nn < 4; nn++) {
            int col = n0 + warpN * 32 + nn * 8 + (lane & 3) * 2;
#pragma unroll
            for (int h = 0; h < 2; h++) {
                int row = m0 + warpM * 64 + mt * 16 + (lane >> 2) + h * 8;
                size_t o = (size_t)row * Ncols + col;
                float2 ov; ov.x = acc[mt][nn][h * 2 + 0]; ov.y = acc[mt][nn][h * 2 + 1];
                *(float2*)(C + o) = ov;
            }
        }
    }
#undef LOAD_STAGE
}

// ---------------- fp32 SIMT GEMM (output path; validated R1 code) -------------
// C[m, n] = A[m, :Kd] x B[Kd, ldb] cols n0.. (+ epilogue)
// EPI: 1 +bias, 2 +bias+gelu, 3 +bias+res
template <int EPI>
__global__ void gemm_kernel(const float* __restrict__ A,
                            const float* __restrict__ B,
                            const float* __restrict__ bias,
                            const float* __restrict__ res,
                            float* __restrict__ C,
                            int Kd, int ldb, int Ncols) {
    __shared__ float As[16][64];
    __shared__ float Bs[16][64];
    int tid = threadIdx.x;
    int tx = tid & 15, ty = tid >> 4;
    int m0 = blockIdx.y * 64, n0 = blockIdx.x * 64;

    float acc[4][4] = {};

    int ar = tid >> 2;
    int ac4 = (tid & 3) * 4;
    const float* Aptr = A + (size_t)(m0 + ar) * Kd + ac4;
    int br = tid >> 4;
    int bc4 = (tid & 15) * 4;
    const float* Bptr = B + (size_t)br * ldb + n0 + bc4;

    for (int k0 = 0; k0 < Kd; k0 += 16) {
        float4 av = *(const float4*)(Aptr + k0);
        float4 bv = *(const float4*)(Bptr + (size_t)k0 * ldb);
        __syncthreads();
        As[ac4 + 0][ar] = av.x; As[ac4 + 1][ar] = av.y;
        As[ac4 + 2][ar] = av.z; As[ac4 + 3][ar] = av.w;
        *(float4*)&Bs[br][bc4] = bv;
        __syncthreads();
#pragma unroll
        for (int k = 0; k < 16; k++) {
            float4 a = *(const float4*)&As[k][ty * 4];
            float4 b = *(const float4*)&Bs[k][tx * 4];
            acc[0][0] += a.x * b.x; acc[0][1] += a.x * b.y; acc[0][2] += a.x * b.z; acc[0][3] += a.x * b.w;
            acc[1][0] += a.y * b.x; acc[1][1] += a.y * b.y; acc[1][2] += a.y * b.z; acc[1][3] += a.y * b.w;
            acc[2][0] += a.z * b.x; acc[2][1] += a.z * b.y; acc[2][2] += a.z * b.z; acc[2][3] += a.z * b.w;
            acc[3][0] += a.w * b.x; acc[3][1] += a.w * b.y; acc[3][2] += a.w * b.z; acc[3][3] += a.w * b.w;
        }
    }

#pragma unroll
    for (int i = 0; i < 4; i++) {
        int row = m0 + ty * 4 + i;
        size_t base = (size_t)row * Ncols;
#pragma unroll
        for (int j = 0; j < 4; j++) {
            int col = n0 + tx * 4 + j;
            float v = acc[i][j];
            if (EPI >= 1) v += bias[col];
            if (EPI == 2) v = gelu_new(v);
            if (EPI == 3) v += res[base + col];
            C[base + col] = v;
        }
    }
}

// ---------------- pre-pass: fp32 -> bf16 convert ------------------------------
__global__ void cvt_kernel(const float* __restrict__ in, __nv_bfloat16* __restrict__ out, int n) {
    int i = blockIdx.x * 256 + threadIdx.x;
    if (i < n) out[i] = __float2bfloat16_rn(in[i]);
}

// ---------------- layernorm ---------------------------------------------------
__global__ void ln_kernel(const float* __restrict__ x,
                          const float* __restrict__ g,
                          const float* __restrict__ b,
                          float* __restrict__ out) {
    int row = blockIdx.x;
    int t = threadIdx.x;
    const float* xr = x + (size_t)row * DMODEL;
    float v[3];
#pragma unroll
    for (int i = 0; i < 3; i++) v[i] = xr[t + i * 256];
    float s = 0.f, s2 = 0.f;
#pragma unroll
    for (int i = 0; i < 3; i++) { s += v[i]; s2 += v[i] * v[i]; }
#pragma unroll
    for (int o = 16; o; o >>= 1) {
        s  += __shfl_down_sync(0xffffffffu, s, o);
        s2 += __shfl_down_sync(0xffffffffu, s2, o);
    }
    __shared__ float ws[8], ws2[8];
    int w = t >> 5, l = t & 31;
    if (l == 0) { ws[w] = s; ws2[w] = s2; }
    __syncthreads();
    if (t == 0) {
        float a = 0.f, a2 = 0.f;
#pragma unroll
        for (int i = 0; i < 8; i++) { a += ws[i]; a2 += ws2[i]; }
        float mu = a / DMODEL;
        ws[0] = mu;
        ws2[0] = a2 / DMODEL - mu * mu;
    }
    __syncthreads();
    float mu = ws[0];
    float rstd = rsqrtf(ws2[0] + 1e-5f);
    float* orow = out + (size_t)row * DMODEL;
#pragma unroll
    for (int i = 0; i < 3; i++) {
        int c = t + i * 256;
        orow[c] = (v[i] - mu) * rstd * g[c] + b[c];
    }
}

// ---------------- top-32 shortlist per row over 32768 scores -----------------
__global__ void topk32_kernel() {
    int row = blockIdx.x;
    int t = threadIdx.x;
    const float* s = g_scores + (size_t)row * MDB;

    float lv[KSHORT];
    int   li[KSHORT];
#pragma unroll
    for (int i = 0; i < KSHORT; i++) { lv[i] = -FLT_MAX; li[i] = 0x7fffffff; }

    for (int j = t; j < MDB; j += 256) {
        float v = s[j];
        if (v > lv[KSHORT - 1]) {
            int p = KSHORT - 1;
            while (p > 0 && lv[p - 1] < v) {
                lv[p] = lv[p - 1]; li[p] = li[p - 1]; p--;
            }
            lv[p] = v; li[p] = j;
        }
    }

    __shared__ float cv[256];
    __shared__ int   ci[256];
    __shared__ int   ctid[256];
    int p = 0;
    for (int rnd = 0; rnd < KSHORT; rnd++) {
        cv[t] = (p < KSHORT) ? lv[p] : -FLT_MAX;
        ci[t] = (p < KSHORT) ? li[p] : 0x7fffffff;
        ctid[t] = t;
        __syncthreads();
        for (int off = 128; off > 0; off >>= 1) {
            if (t < off) {
                float a = cv[t], b = cv[t + off];
                if (b > a || (b == a && ci[t + off] < ci[t])) {
                    cv[t] = b; ci[t] = ci[t + off]; ctid[t] = ctid[t + off];
                }
            }
            __syncthreads();
        }
        int wt = ctid[0];
        if (t == 0) g_idx32[row * KSHORT + rnd] = ci[0];
        __syncthreads();
        if (t == wt) p++;
    }
}

// ---------------- fp32 rescore of 32 candidates, exact top-16 ----------------
__global__ void rescore_kernel(const float* __restrict__ dbk) {
    int tok = blockIdx.x;
    int t = threadIdx.x;
    int w = t >> 5, l = t & 31;

    __shared__ float qs[DMODEL];
    __shared__ int   cands[KSHORT];
    __shared__ float svals[KSHORT];

    if (t < KSHORT) cands[t] = g_idx32[tok * KSHORT + t];
    for (int i = t; i < DMODEL; i += 256) qs[i] = g_q[(size_t)tok * DMODEL + i];
    __syncthreads();

#pragma unroll
    for (int cc = 0; cc < 4; cc++) {
        int cidx = w * 4 + cc;
        const float* kr = dbk + (size_t)cands[cidx] * DMODEL;
        float d = 0.f;
        for (int j = l; j < DMODEL; j += 32) d += qs[j] * kr[j];
#pragma unroll
        for (int o = 16; o; o >>= 1) d += __shfl_xor_sync(0xffffffffu, d, o);
        if (l == 0) svals[cidx] = d;
    }
    __syncthreads();

    if (t < 32) {
        float v = svals[t];
        int   ci = cands[t];
#pragma unroll
        for (int rnd = 0; rnd < KSEL; rnd++) {
            float bv = v;
            int bl = t;
#pragma unroll
            for (int o = 16; o; o >>= 1) {
                float ov = __shfl_xor_sync(0xffffffffu, bv, o);
                int   ol = __shfl_xor_sync(0xffffffffu, bl, o);
                if (ov > bv || (ov == bv && ol < bl)) { bv = ov; bl = ol; }
            }
            int wci = __shfl_sync(0xffffffffu, ci, bl);
            if (t == 0) g_idx[tok * KSEL + rnd] = wci;
            if (t == bl) v = -FLT_MAX;
        }
    }
}

// ---------------- gather + per-token softmax attention ------------------------
__global__ void attn_kernel(const float* __restrict__ dbk,
                            const float* __restrict__ dbv) {
    int tok = blockIdx.x;
    int t = threadIdx.x;
    int w = t >> 5, l = t & 31;

    __shared__ float qs[DMODEL];
    __shared__ int   idxs[KSEL];
    __shared__ float sc[NHEAD * KSEL];
    __shared__ float wts[NHEAD * KSEL];

    if (t < KSEL) idxs[t] = g_idx[tok * KSEL + t];
    for (int i = t; i < DMODEL; i += 128) qs[i] = g_q[(size_t)tok * DMODEL + i];
    __syncthreads();

    for (int pp = w * 48; pp < (w + 1) * 48; pp++) {
        int h = pp >> 4, k = pp & 15;
        const float* kr = dbk + (size_t)idxs[k] * DMODEL + h * HDIM;
        float2 kv = ((const float2*)kr)[l];
        float2 qv = ((const float2*)(qs + h * HDIM))[l];
        float d = kv.x * qv.x + kv.y * qv.y;
#pragma unroll
        for (int o = 16; o; o >>= 1) d += __shfl_xor_sync(0xffffffffu, d, o);
        if (l == 0) sc[pp] = d * 0.125f;
    }
    __syncthreads();

    if (t < NHEAD) {
        float mx = -FLT_MAX;
#pragma unroll
        for (int k = 0; k < KSEL; k++) mx = fmaxf(mx, sc[t * KSEL + k]);
        float sum = 0.f;
#pragma unroll
        for (int k = 0; k < KSEL; k++) {
            float e = expf(sc[t * KSEL + k] - mx);
            wts[t * KSEL + k] = e;
            sum += e;
        }
        float inv = 1.0f / sum;
#pragma unroll
        for (int k = 0; k < KSEL; k++) wts[t * KSEL + k] *= inv;
    }
    __syncthreads();

    float acc[6] = {0.f, 0.f, 0.f, 0.f, 0.f, 0.f};
    int hh[6];
#pragma unroll
    for (int j = 0; j < 6; j++) hh[j] = (t + j * 128) >> 6;
    for (int k = 0; k < KSEL; k++) {
        const float* vr = dbv + (size_t)idxs[k] * DMODEL;
#pragma unroll
        for (int j = 0; j < 6; j++) {
            acc[j] += wts[hh[j] * KSEL + k] * vr[t + j * 128];
        }
    }
    float* orow = g_attn + (size_t)tok * DMODEL;
#pragma unroll
    for (int j = 0; j < 6; j++) orow[t + j * 128] = acc[j];
}

// ---------------- launch ------------------------------------------------------
#define GEMM_SMEM (4 * 32768)

extern "C" void kernel_launch(void* const* d_in, const int* in_sizes, int n_in,
                              void* d_out, int out_size) {
    const float* prev     = (const float*)d_in[0];
    const float* db_keys  = (const float*)d_in[1];
    const float* db_vals  = (const float*)d_in[2];
    const float* ln1_g    = (const float*)d_in[3];
    const float* ln1_b    = (const float*)d_in[4];
    const float* c_attn_w = (const float*)d_in[5];
    const float* c_attn_b = (const float*)d_in[6];
    const float* c_proj_w = (const float*)d_in[7];
    const float* c_proj_b = (const float*)d_in[8];
    const float* ln2_g    = (const float*)d_in[9];
    const float* ln2_b    = (const float*)d_in[10];
    const float* fc_w     = (const float*)d_in[11];
    const float* fc_b     = (const float*)d_in[12];
    const float* proj_w   = (const float*)d_in[13];
    const float* proj_b   = (const float*)d_in[14];
    float* out = (float*)d_out;

    float *p_h1, *p_q, *p_scores, *p_attn, *p_res2, *p_h2, *p_ff;
    __nv_bfloat16 *p_keys, *p_qb;
    cudaGetSymbolAddress((void**)&p_h1, g_h1);
    cudaGetSymbolAddress((void**)&p_q, g_q);
    cudaGetSymbolAddress((void**)&p_scores, g_scores);
    cudaGetSymbolAddress((void**)&p_attn, g_attn);
    cudaGetSymbolAddress((void**)&p_res2, g_res2);
    cudaGetSymbolAddress((void**)&p_h2, g_h2);
    cudaGetSymbolAddress((void**)&p_ff, g_ff);
    cudaGetSymbolAddress((void**)&p_keys, g_keys_bf);
    cudaGetSymbolAddress((void**)&p_qb, g_qb);

    cudaFuncSetAttribute(bgemm, cudaFuncAttributeMaxDynamicSharedMemorySize, GEMM_SMEM);

    // 0. convert db_keys to bf16 (scores B operand)
    cvt_kernel<<<(MDB * DMODEL + 255) / 256, 256>>>(db_keys, p_keys, MDB * DMODEL);
    // 1. LN1
    ln_kernel<<<NTOK, 256>>>(prev, ln1_g, ln1_b, p_h1);
    // 2. q projection (q third of c_attn) — fp32 SIMT (validated)
    gemm_kernel<1><<<dim3(DMODEL / 64, NTOK / 64), 256>>>(
        p_h1, c_attn_w, c_attn_b, nullptr, p_q, DMODEL, 3 * DMODEL, DMODEL);
    // 3. KNN scores: q(bf16) @ keys(bf16)^T — bf16 HMMA (selection fixed by rescore)
    cvt_kernel<<<(NTOK * DMODEL + 255) / 256, 256>>>(p_q, p_qb, NTOK * DMODEL);
    bgemm<<<dim3(NTOK / 128, MDB / 128), 256, GEMM_SMEM>>>(
        p_qb, p_keys, p_scores, DMODEL, MDB);
    // 4. top-32 shortlist
    topk32_kernel<<<NTOK, 256>>>();
    // 5. exact fp32 rescore -> top-16
    rescore_kernel<<<NTOK, 256>>>(db_keys);
    // 6. gather + per-token memory attention
    attn_kernel<<<NTOK, 128>>>(db_keys, db_vals);
    // 7. c_proj + residual — fp32 SIMT
    gemm_kernel<3><<<dim3(DMODEL / 64, NTOK / 64), 256>>>(
        p_attn, c_proj_w, c_proj_b, prev, p_res2, DMODEL, DMODEL, DMODEL);
    // 8. LN2
    ln_kernel<<<NTOK, 256>>>(p_res2, ln2_g, ln2_b, p_h2);
    // 9. MLP fc + gelu — fp32 SIMT
    gemm_kernel<2><<<dim3(DFF / 64, NTOK / 64), 256>>>(
        p_h2, fc_w, fc_b, nullptr, p_ff, DMODEL, DFF, DFF);
    // 10. MLP proj + bias + residual2 -> out — fp32 SIMT
    gemm_kernel<3><<<dim3(DMODEL / 64, NTOK / 64), 256>>>(
        p_ff, proj_w, proj_b, p_res2, out, DFF, DMODEL, DMODEL);
}